// round 1
// baseline (speedup 1.0000x reference)
#include <cuda_runtime.h>
#include <math.h>

#define TT 4
#define NN 50000
#define EE 400000
#define CAP 2048

// ---------------- scratch (device globals: allocation-free) ----------------
__device__ float g_XW[NN * 128];          // GEMM output (layer1 uses NN*64 of it)
__device__ float g_X1[NN * 128];          // h1[t] (layer0 output at current t)
__device__ float g_scores[NN];
__device__ unsigned g_hist[4096];
__device__ int g_ctrl[4];                 // [0]=bstar [1]=count_above [2]=ncand
__device__ unsigned long long g_cand[CAP];
__device__ int g_tidx[128];
__device__ float g_ttanh[128];
__device__ float g_z[128 * 128];          // zT: [k][128], zT[j][r] = z[r][j]
__device__ float g_Q0s[128 * 128];
__device__ float g_Q1s[128 * 64];
__device__ float g_upd[128 * 128];
__device__ float g_rstq[128 * 128];
__device__ float g_snorm[2];
__device__ int g_cnt[NN];
__device__ int g_off[NN + 1];
__device__ int g_es[EE];
__device__ float g_ew[EE];

__device__ __forceinline__ float* Qptr(int lay) { return lay ? g_Q1s : g_Q0s; }
__device__ __forceinline__ unsigned mono(float f) {
    unsigned u = __float_as_uint(f);
    return (u & 0x80000000u) ? ~u : (u | 0x80000000u);
}
__device__ __forceinline__ float sigm(float x) { return 1.f / (1.f + expf(-x)); }

// ---------------- small utility kernels ----------------
__global__ void k_copyQ(const float* __restrict__ src, int lay, int n) {
    int i = blockIdx.x * blockDim.x + threadIdx.x;
    if (i < n) Qptr(lay)[i] = src[i];
}

__global__ void k_snorm(const float* __restrict__ sc, int lay) {
    __shared__ float sh[128];
    int t = threadIdx.x;
    float v = sc[t];
    sh[t] = v * v;
    __syncthreads();
    for (int o = 64; o > 0; o >>= 1) {
        if (t < o) sh[t] += sh[t + o];
        __syncthreads();
    }
    if (t == 0) g_snorm[lay] = sqrtf(sh[0]);
}

__global__ void k_zero_hist() {  // zeros g_hist + g_ctrl
    int i = blockIdx.x * blockDim.x + threadIdx.x;
    if (i < 4096) g_hist[i] = 0u;
    if (i < 4) g_ctrl[i] = 0;
}

__global__ void k_zero_cnt() {
    int i = blockIdx.x * blockDim.x + threadIdx.x;
    if (i < NN) g_cnt[i] = 0;
}

// ---------------- scores + exact top-k (radix select + bitonic) ----------------
__global__ void k_scores(const float* __restrict__ X, const float* __restrict__ m,
                         const float* __restrict__ scorer, int lay) {
    const float* Xp = X ? X : g_X1;
    int gt = blockIdx.x * blockDim.x + threadIdx.x;
    int n = gt >> 5, lane = gt & 31;
    if (n >= NN) return;
    const float* xr = Xp + (size_t)n * 128;
    float acc = xr[lane] * scorer[lane] + xr[lane + 32] * scorer[lane + 32] +
                xr[lane + 64] * scorer[lane + 64] + xr[lane + 96] * scorer[lane + 96];
#pragma unroll
    for (int o = 16; o; o >>= 1) acc += __shfl_xor_sync(0xffffffffu, acc, o);
    if (lane == 0) g_scores[n] = acc / g_snorm[lay] + m[n];
}

__global__ void k_hist() {
    __shared__ unsigned sh[4096];
    for (int i = threadIdx.x; i < 4096; i += blockDim.x) sh[i] = 0u;
    __syncthreads();
    int stride = gridDim.x * blockDim.x;
    for (int i = blockIdx.x * blockDim.x + threadIdx.x; i < NN; i += stride)
        atomicAdd(&sh[mono(g_scores[i]) >> 20], 1u);
    __syncthreads();
    for (int i = threadIdx.x; i < 4096; i += blockDim.x)
        if (sh[i]) atomicAdd(&g_hist[i], sh[i]);
}

__global__ void k_findbucket(int k) {  // 1024 threads
    __shared__ unsigned sh[1024];
    int tid = threadIdx.x;
    int c0 = tid * 4;
    unsigned h0 = g_hist[c0], h1 = g_hist[c0 + 1], h2 = g_hist[c0 + 2], h3 = g_hist[c0 + 3];
    sh[tid] = h0 + h1 + h2 + h3;
    __syncthreads();
    for (int o = 1; o < 1024; o <<= 1) {  // inclusive suffix scan
        unsigned v = (tid + o < 1024) ? sh[tid + o] : 0u;
        __syncthreads();
        sh[tid] += v;
        __syncthreads();
    }
    unsigned above = (tid < 1023) ? sh[tid + 1] : 0u;
    unsigned hh[4] = {h0, h1, h2, h3};
    for (int b = 3; b >= 0; --b) {
        unsigned cnt = hh[b];
        if (above < (unsigned)k && above + cnt >= (unsigned)k) {
            g_ctrl[0] = c0 + b;
            g_ctrl[1] = (int)above;
        }
        above += cnt;
    }
}

__global__ void k_compact() {
    int bstar = g_ctrl[0];
    int stride = gridDim.x * blockDim.x;
    for (int i = blockIdx.x * blockDim.x + threadIdx.x; i < NN; i += stride) {
        unsigned key = mono(g_scores[i]);
        if ((int)(key >> 20) >= bstar) {
            int p = atomicAdd(&g_ctrl[2], 1);
            if (p < CAP)
                g_cand[p] = ((unsigned long long)key << 32) | (unsigned long long)(0xFFFFFFFFu - (unsigned)i);
        }
    }
}

__global__ void k_sortselect(int k) {  // 1024 threads, CAP=2048 bitonic (descending)
    __shared__ unsigned long long s[CAP];
    int tid = threadIdx.x;
    int n = g_ctrl[2];
    if (n > CAP) n = CAP;
    for (int i = tid; i < CAP; i += 1024) s[i] = (i < n) ? g_cand[i] : 0ULL;
    __syncthreads();
    for (int size = 2; size <= CAP; size <<= 1)
        for (int stride = size >> 1; stride > 0; stride >>= 1) {
            for (int i = tid; i < CAP; i += 1024) {
                int j = i ^ stride;
                if (j > i) {
                    unsigned long long a = s[i], b = s[j];
                    bool desc = ((i & size) == 0);
                    if (desc ? (a < b) : (a > b)) { s[i] = b; s[j] = a; }
                }
            }
            __syncthreads();
        }
    if (tid < k) {
        unsigned long long c = s[tid];
        unsigned idx = 0xFFFFFFFFu - (unsigned)(c & 0xFFFFFFFFu);
        g_tidx[tid] = (int)idx;
        g_ttanh[tid] = tanhf(g_scores[idx]);
    }
}

__global__ void k_buildz(const float* __restrict__ X) {  // grid = COLS blocks x 128 thr
    const float* Xp = X ? X : g_X1;
    int j = blockIdx.x, r = threadIdx.x;
    g_z[j * 128 + r] = Xp[(size_t)g_tidx[j] * 128 + r] * g_ttanh[j];
}

// ---------------- GRU weight evolution ----------------
__global__ void k_gru1(const float* __restrict__ Wu, const float* __restrict__ Uu,
                       const float* __restrict__ Bu, const float* __restrict__ Wr,
                       const float* __restrict__ Ur, const float* __restrict__ Br,
                       int lay, int COLS) {
    int idx = blockIdx.x * blockDim.x + threadIdx.x;
    if (idx >= 128 * COLS) return;
    int c = idx % COLS, r = idx / COLS;
    const float* Q = Qptr(lay);
    float su = 0, sr = 0, qu = 0, qr = 0;
#pragma unroll 4
    for (int i = 0; i < 128; i++) {
        float zi = g_z[c * 128 + i];
        su += Wu[r * 128 + i] * zi;
        sr += Wr[r * 128 + i] * zi;
        float qi = Q[i * COLS + c];
        qu += Uu[r * 128 + i] * qi;
        qr += Ur[r * 128 + i] * qi;
    }
    float u = sigm(su + qu + Bu[r * COLS + c]);
    float rs = sigm(sr + qr + Br[r * COLS + c]);
    g_upd[r * COLS + c] = u;
    g_rstq[r * COLS + c] = rs * Q[r * COLS + c];
}

__global__ void k_gru2(const float* __restrict__ Wh, const float* __restrict__ Uh,
                       const float* __restrict__ Bh, int lay, int COLS) {
    int idx = blockIdx.x * blockDim.x + threadIdx.x;
    if (idx >= 128 * COLS) return;
    int c = idx % COLS, r = idx / COLS;
    float* Q = Qptr(lay);
    float h = 0;
#pragma unroll 4
    for (int i = 0; i < 128; i++) {
        h += Wh[r * 128 + i] * g_z[c * 128 + i];
        h += Uh[r * 128 + i] * g_rstq[i * COLS + c];
    }
    float hc = tanhf(h + Bh[r * COLS + c]);
    float u = g_upd[r * COLS + c];
    float q = Q[r * COLS + c];
    Q[r * COLS + c] = (1.f - u) * q + u * hc;
}

// ---------------- SGEMM: XW = X[N,128] @ Q[128,BN] ----------------
template <int BN>
__global__ void __launch_bounds__(256) k_gemm(const float* __restrict__ X, int lay) {
    constexpr int TN = BN / 16;  // 8 (BN=128) or 4 (BN=64)
    const float* A = X ? X : g_X1;
    const float* B = lay ? g_Q1s : g_Q0s;
    __shared__ float As[8][132];
    __shared__ float Bs[8][BN];
    int tid = threadIdx.x;
    int tx = tid & 15, ty = tid >> 4;
    int row0 = blockIdx.x * 128;
    float acc[8][TN];
#pragma unroll
    for (int m = 0; m < 8; m++)
#pragma unroll
        for (int n2 = 0; n2 < TN; n2++) acc[m][n2] = 0.f;
    int lr = tid >> 1, lk = (tid & 1) * 4;
    for (int k0 = 0; k0 < 128; k0 += 8) {
        float4 a4 = make_float4(0.f, 0.f, 0.f, 0.f);
        int gr = row0 + lr;
        if (gr < NN) a4 = *(const float4*)(A + (size_t)gr * 128 + k0 + lk);
        As[lk + 0][lr] = a4.x;
        As[lk + 1][lr] = a4.y;
        As[lk + 2][lr] = a4.z;
        As[lk + 3][lr] = a4.w;
        if (BN == 128) {
            int kb = tid >> 5, cb = (tid & 31) * 4;
            *(float4*)&Bs[kb][cb] = *(const float4*)(B + (k0 + kb) * BN + cb);
        } else {
            int kb = tid >> 5, cb = (tid & 31) * 2;
            *(float2*)&Bs[kb][cb] = *(const float2*)(B + (k0 + kb) * BN + cb);
        }
        __syncthreads();
#pragma unroll
        for (int kk = 0; kk < 8; kk++) {
            float ra[8], rb[TN];
#pragma unroll
            for (int m = 0; m < 8; m++) ra[m] = As[kk][ty * 8 + m];
#pragma unroll
            for (int n2 = 0; n2 < TN; n2++) rb[n2] = Bs[kk][tx * TN + n2];
#pragma unroll
            for (int m = 0; m < 8; m++)
#pragma unroll
                for (int n2 = 0; n2 < TN; n2++) acc[m][n2] += ra[m] * rb[n2];
        }
        __syncthreads();
    }
#pragma unroll
    for (int m = 0; m < 8; m++) {
        int gr = row0 + ty * 8 + m;
        if (gr < NN)
#pragma unroll
            for (int n2 = 0; n2 < TN; n2++) g_XW[(size_t)gr * BN + tx * TN + n2] = acc[m][n2];
    }
}

// ---------------- CSR build (once per timestep) ----------------
__global__ void k_histdst(const int* __restrict__ dst) {
    int stride = gridDim.x * blockDim.x;
    for (int e = blockIdx.x * blockDim.x + threadIdx.x; e < EE; e += stride)
        atomicAdd(&g_cnt[dst[e]], 1);
}

__global__ void k_scan() {  // 1024 threads, exclusive scan of g_cnt -> g_off
    __shared__ int wsum[32];
    __shared__ int s_carry;
    int tid = threadIdx.x, lane = tid & 31, wid = tid >> 5;
    if (tid == 0) s_carry = 0;
    __syncthreads();
    for (int base = 0; base < NN; base += 1024) {
        int i = base + tid;
        int c = (i < NN) ? g_cnt[i] : 0;
        int v = c;
#pragma unroll
        for (int o = 1; o < 32; o <<= 1) {
            int nv = __shfl_up_sync(0xffffffffu, v, o);
            if (lane >= o) v += nv;
        }
        if (lane == 31) wsum[wid] = v;
        __syncthreads();
        if (wid == 0) {
            int wv = wsum[lane];
#pragma unroll
            for (int o = 1; o < 32; o <<= 1) {
                int nv = __shfl_up_sync(0xffffffffu, wv, o);
                if (lane >= o) wv += nv;
            }
            wsum[lane] = wv;
        }
        __syncthreads();
        int pre = (wid > 0) ? wsum[wid - 1] : 0;
        int incl = v + pre;
        if (i < NN) g_off[i] = s_carry + incl - c;
        int total = wsum[31];
        __syncthreads();
        if (tid == 0) s_carry += total;
        __syncthreads();
    }
    if (tid == 0) g_off[NN] = s_carry;
}

__global__ void k_place(const int* __restrict__ src, const int* __restrict__ dst,
                        const float* __restrict__ w) {
    int stride = gridDim.x * blockDim.x;
    for (int e = blockIdx.x * blockDim.x + threadIdx.x; e < EE; e += stride) {
        int d = dst[e];
        int p = g_off[d] + atomicAdd(&g_cnt[d], 1);
        g_es[p] = src[e];
        g_ew[p] = w[e];
    }
}

// ---------------- atomic-free gather segment-sum + relu ----------------
__global__ void k_spmm128(float* out) {  // out==nullptr -> g_X1
    int gt = blockIdx.x * blockDim.x + threadIdx.x;
    int n = gt >> 5, lane = gt & 31;
    if (n >= NN) return;
    int beg = g_off[n], end = g_off[n + 1];
    const float4* X4 = (const float4*)g_XW;
    float4 a = make_float4(0.f, 0.f, 0.f, 0.f);
    for (int j = beg; j < end; ++j) {
        int s = g_es[j];
        float wt = g_ew[j];
        float4 v = X4[(size_t)s * 32 + lane];
        a.x += v.x * wt; a.y += v.y * wt; a.z += v.z * wt; a.w += v.w * wt;
    }
    float4 r = make_float4(fmaxf(a.x, 0.f), fmaxf(a.y, 0.f), fmaxf(a.z, 0.f), fmaxf(a.w, 0.f));
    float* o = out ? out : g_X1;
    ((float4*)o)[(size_t)n * 32 + lane] = r;
}

__global__ void k_spmm64(float* out) {
    int gt = blockIdx.x * blockDim.x + threadIdx.x;
    int n = gt >> 5, lane = gt & 31;
    if (n >= NN) return;
    int beg = g_off[n], end = g_off[n + 1];
    const float2* X2 = (const float2*)g_XW;
    float2 a = make_float2(0.f, 0.f);
    for (int j = beg; j < end; ++j) {
        int s = g_es[j];
        float wt = g_ew[j];
        float2 v = X2[(size_t)s * 32 + lane];
        a.x += v.x * wt; a.y += v.y * wt;
    }
    float2 r = make_float2(fmaxf(a.x, 0.f), fmaxf(a.y, 0.f));
    ((float2*)out)[(size_t)n * 32 + lane] = r;
}

// ---------------- host orchestration ----------------
static void layer_step(const float* X, const float* m, const float* const* p, int lay,
                       int COLS, float* outp) {
    k_scores<<<(NN * 32 + 255) / 256, 256>>>(X, m, p[9], lay);
    k_zero_hist<<<4, 1024>>>();
    k_hist<<<148, 256>>>();
    k_findbucket<<<1, 1024>>>(COLS);
    k_compact<<<148, 256>>>();
    k_sortselect<<<1, 1024>>>(COLS);
    k_buildz<<<COLS, 128>>>(X);
    k_gru1<<<(128 * COLS + 255) / 256, 256>>>(p[0], p[1], p[2], p[3], p[4], p[5], lay, COLS);
    k_gru2<<<(128 * COLS + 255) / 256, 256>>>(p[6], p[7], p[8], lay, COLS);
    if (COLS == 128) {
        k_gemm<128><<<(NN + 127) / 128, 256>>>(X, lay);
        k_spmm128<<<(NN * 32 + 255) / 256, 256>>>(outp);
    } else {
        k_gemm<64><<<(NN + 127) / 128, 256>>>(X, lay);
        k_spmm64<<<(NN * 32 + 255) / 256, 256>>>(outp);
    }
}

extern "C" void kernel_launch(void* const* d_in, const int* in_sizes, int n_in,
                              void* d_out, int out_size) {
    const float* node_embs = (const float*)d_in[0];
    const float* mask = (const float*)d_in[1];
    const int* esrc = (const int*)d_in[2];
    const int* edst = (const int*)d_in[3];
    const float* ew = (const float*)d_in[4];
    const float* w0 = (const float*)d_in[5];
    const float* w1 = (const float*)d_in[6];
    const float* p0[10];
    const float* p1[10];
    for (int i = 0; i < 10; i++) p0[i] = (const float*)d_in[7 + i];
    for (int i = 0; i < 10; i++) p1[i] = (const float*)d_in[17 + i];
    float* out = (float*)d_out;

    k_snorm<<<1, 128>>>(p0[9], 0);
    k_snorm<<<1, 128>>>(p1[9], 1);
    k_copyQ<<<(128 * 128 + 255) / 256, 256>>>(w0, 0, 128 * 128);
    k_copyQ<<<(128 * 64 + 255) / 256, 256>>>(w1, 1, 128 * 64);

    for (int t = 0; t < TT; t++) {
        // CSR by destination (shared by both layers)
        k_zero_cnt<<<49, 1024>>>();
        k_histdst<<<(EE + 255) / 256, 256>>>(edst + (size_t)t * EE);
        k_scan<<<1, 1024>>>();
        k_zero_cnt<<<49, 1024>>>();
        k_place<<<(EE + 255) / 256, 256>>>(esrc + (size_t)t * EE, edst + (size_t)t * EE,
                                           ew + (size_t)t * EE);
        // layer 0: X = node_embs[t], out -> g_X1
        layer_step(node_embs + (size_t)t * NN * 128, mask + (size_t)t * NN, p0, 0, 128, nullptr);
        // layer 1: X = g_X1 (nullptr sentinel), out -> d_out[t]
        layer_step(nullptr, mask + (size_t)t * NN, p1, 1, 64, out + (size_t)t * NN * 64);
    }
}